// round 9
// baseline (speedup 1.0000x reference)
#include <cuda_runtime.h>
#include <math.h>
#include <stdint.h>

#define Dd 128
#define Hh 512
#define Ww 512
#define OD 32
#define HW (Hh*Ww)
#define INV_SQRT_2PI 0.3989422804014327f

#define NT 288
#define PLANE 5184          // 72*72 halo floats
#define SIN 76              // padded stride for xy phases
#define RING_F (3*PLANE)    // 3-stage ring
#define SMEM_DYN ((RING_F + 72*SIN) * 4)   // 62208 + 21888 = 84096 B

__device__ unsigned g_minb;
__device__ unsigned g_maxb;

__device__ __forceinline__ unsigned f2o(float f) {
    unsigned u = __float_as_uint(f);
    return (u & 0x80000000u) ? ~u : (u | 0x80000000u);
}
__device__ __forceinline__ float o2f(unsigned u) {
    return (u & 0x80000000u) ? __uint_as_float(u ^ 0x80000000u)
                             : __uint_as_float(~u);
}

// ---------------------------------------------------------------------------
// Fused kernel: z-conv (stride 4, 9 taps) + y-conv + x-conv + min/max.
// Block = 64x64 (x,y) output tile x 8 output z-planes.
// Streams 37 input-plane halos (72x72) via 3-stage cp.async ring; rolling
// register accumulators (3 live x 18 elems/thread); every 4th plane retires
// one z-convolved halo plane through smem -> y-conv in place -> x-conv ->
// global store with running min/max.  No intermediate global scratch.
// RING IS CROSS-THREAD: __syncthreads() after wait_group (visibility) and
// after the register copy-out (safe slot reuse) — this was the R8 race.
// ---------------------------------------------------------------------------
__global__ void __launch_bounds__(NT, 2) k_fused(
    const float* __restrict__ in,
    const float* __restrict__ p_mu, const float* __restrict__ p_sig,
    const float* __restrict__ p_bxy, const float* __restrict__ p_bz,
    float* __restrict__ out)
{
    extern __shared__ __align__(16) float smem[];
    float* ring = smem;                 // [3][5184]
    float* s_pl = smem + RING_F;        // [72][76]
    __shared__ float smin[16], smax[16];

    int t   = threadIdx.x;
    int Y0  = blockIdx.x * 64;
    int X0  = blockIdx.y * 64;
    int zo0 = blockIdx.z * 8;
    int zstart = 4 * zo0 - 3;           // input plane at iz=0 (37 planes)

    unsigned sring = (unsigned)__cvta_generic_to_shared(ring);

    uint64_t pol_f;
    asm("createpolicy.fractional.L2::evict_first.b64 %0, 1.0;" : "=l"(pol_f));

    float bz = *p_bz, bxy = *p_bxy;
    float amp = INV_SQRT_2PI * expf(*p_mu + 0.5f * (*p_sig) * (*p_sig));
    float i2bz = 1.0f / (2.0f * bz * bz);
    float i2bx = 1.0f / (2.0f * bxy * bxy);
    float wz[9], w[9];
#pragma unroll
    for (int k = 0; k < 9; k++) {
        float d = (float)(k - 4);
        wz[k] = expf(-d * d * i2bz) * amp;
        w[k]  = expf(-d * d * i2bx);
    }

    float acc[3][18];
#pragma unroll
    for (int s = 0; s < 3; s++)
#pragma unroll
        for (int j = 0; j < 18; j++) acc[s][j] = 0.f;

    float lmin =  3.402823466e38f;
    float lmax = -3.402823466e38f;

    // stage plane P (0..36) into ring slot P%3; 1296 float4 granules
#define ISSUE(P) do { if ((P) <= 36) {                                        \
        int z_ = zstart + (P);                                                \
        int zok_ = ((unsigned)z_ < 128u);                                     \
        const float* pz_ = in + (size_t)(zok_ ? z_ : 0) * HW;                 \
        _Pragma("unroll")                                                     \
        for (int i5 = 0; i5 < 5; i5++) {                                      \
            int i_ = t + i5 * NT;                                             \
            if (i_ < 1296) {                                                  \
                int r_ = i_ / 18, f_ = i_ % 18;                               \
                int gx_ = X0 - 4 + r_;                                        \
                int gy_ = Y0 - 4 + 4 * f_;                                    \
                int ok_ = (zok_ && (unsigned)gx_ < 512u &&                    \
                           (unsigned)gy_ < 512u) ? 16 : 0;                    \
                int gxc_ = gx_ < 0 ? 0 : (gx_ > 511 ? 511 : gx_);             \
                int gyc_ = gy_ < 0 ? 0 : (gy_ > 508 ? 508 : gy_);             \
                const float* g_ = pz_ + (size_t)gxc_ * 512 + gyc_;            \
                unsigned sa_ = sring +                                        \
                    ((((P) % 3) * PLANE + r_ * 72 + 4 * f_) * 4u);            \
                asm volatile(                                                 \
                    "cp.async.cg.shared.global.L2::cache_hint "               \
                    "[%0], [%1], 16, %2, %3;"                                 \
                    :: "r"(sa_), "l"(g_), "r"(ok_), "l"(pol_f) : "memory");   \
            }                                                                 \
        }                                                                     \
        asm volatile("cp.async.commit_group;" ::: "memory");                  \
    } } while (0)
#define WG(n) asm volatile("cp.async.wait_group " #n ";" ::: "memory")

    ISSUE(0); ISSUE(1); ISSUE(2);

    size_t outbase = (size_t)X0 * 512 + Y0;

#pragma unroll
    for (int iz = 0; iz < 37; iz++) {
        if (iz <= 34)      WG(2);
        else if (iz == 35) WG(1);
        else               WG(0);
        __syncthreads();                // other threads' copies now visible

        // copy my 18 consumption values (cross-thread mapping) to registers
        float v[18];
        const float* st = ring + (iz % 3) * PLANE;
#pragma unroll
        for (int j = 0; j < 18; j++) v[j] = st[t + NT * j];
        __syncthreads();                // slot fully read -> safe to refill

        ISSUE(iz + 3);

        const int c = iz >> 2, q = iz & 3;      // compile-time (full unroll)

        if (c <= 7) {                           // tap kz=q for output j=c
            float wv = wz[q];
            int s = c % 3;
#pragma unroll
            for (int j = 0; j < 18; j++) acc[s][j] += wv * v[j];
        }
        if (c >= 1 && c <= 8) {                 // tap kz=4+q for j=c-1
            float wv = wz[4 + q];
            int s = (c - 1) % 3;
#pragma unroll
            for (int j = 0; j < 18; j++) acc[s][j] += wv * v[j];
        }
        if (q == 0 && c >= 2) {                 // tap kz=8, then RETIRE j=c-2
            const int jout = c - 2;             // 0..7
            const int s = jout % 3;
            float wv = wz[8];
#pragma unroll
            for (int j = 0; j < 18; j++) acc[s][j] += wv * v[j];

            // ---- retire: z-convolved 72x72 plane -> smem ----
#pragma unroll
            for (int j = 0; j < 18; j++) {
                int p = t + NT * j;
                s_pl[(p / 72) * SIN + (p % 72)] = acc[s][j];
                acc[s][j] = 0.f;
            }
            __syncthreads();

            // ---- y-conv, in place (72 rows x 4 segs = 288 threads) ----
            {
                int row = t % 72;
                int c0  = (t / 72) * 16;
                float vy[24];
                float4* vp = reinterpret_cast<float4*>(vy);
#pragma unroll
                for (int g4 = 0; g4 < 6; g4++)
                    vp[g4] = *reinterpret_cast<float4*>(
                        &s_pl[row * SIN + c0 + 4 * g4]);
                __syncthreads();        // all reads before in-place writes
                float r_[16];
#pragma unroll
                for (int o = 0; o < 16; o++) {
                    float sv = 0.f;
#pragma unroll
                    for (int k = 0; k < 9; k++) sv += w[k] * vy[o + k];
                    r_[o] = sv;
                }
#pragma unroll
                for (int g4 = 0; g4 < 4; g4++)
                    *reinterpret_cast<float4*>(&s_pl[row * SIN + c0 + 4 * g4]) =
                        make_float4(r_[4*g4], r_[4*g4+1], r_[4*g4+2], r_[4*g4+3]);
            }
            __syncthreads();

            // ---- x-conv + store + min/max (64 cols x 4 row-segs) ----
            if (t < 256) {
                int col = t & 63;
                int x0  = (t >> 6) * 16;
                float vx[24];
#pragma unroll
                for (int i = 0; i < 24; i++)
                    vx[i] = s_pl[(x0 + i) * SIN + col];
                float* dst = out + (size_t)(zo0 + jout) * HW + outbase
                             + (size_t)x0 * 512 + col;
#pragma unroll
                for (int o = 0; o < 16; o++) {
                    float sv = 0.f;
#pragma unroll
                    for (int k = 0; k < 9; k++) sv += w[k] * vx[o + k];
                    dst[(size_t)o * 512] = sv;
                    lmin = fminf(lmin, sv);
                    lmax = fmaxf(lmax, sv);
                }
            }
            __syncthreads();            // s_pl reused by next retire
        }
    }
#undef ISSUE
#undef WG

    // ---- one block-level min/max reduction + global atomics ----
#pragma unroll
    for (int o = 16; o > 0; o >>= 1) {
        lmin = fminf(lmin, __shfl_xor_sync(0xFFFFFFFFu, lmin, o));
        lmax = fmaxf(lmax, __shfl_xor_sync(0xFFFFFFFFu, lmax, o));
    }
    if ((t & 31) == 0) { smin[t >> 5] = lmin; smax[t >> 5] = lmax; }
    __syncthreads();
    if (t < 16) {
        lmin = (t < 9) ? smin[t] :  3.402823466e38f;
        lmax = (t < 9) ? smax[t] : -3.402823466e38f;
#pragma unroll
        for (int o = 8; o > 0; o >>= 1) {
            lmin = fminf(lmin, __shfl_xor_sync(0x0000FFFFu, lmin, o));
            lmax = fmaxf(lmax, __shfl_xor_sync(0x0000FFFFu, lmax, o));
        }
        if (t == 0) {
            atomicMin(&g_minb, f2o(lmin));
            atomicMax(&g_maxb, f2o(lmax));
        }
    }
}

// ---------------------------------------------------------------------------
// Normalize: in-place min-max on d_out, 2 float4 per thread.
// ---------------------------------------------------------------------------
__global__ void __launch_bounds__(256) k_norm(float4* __restrict__ out)
{
    int i = blockIdx.x * 512 + threadIdx.x;
    float mn = o2f(g_minb);
    float mx = o2f(g_maxb);
    float inv = 1.0f / (mx - mn);
    float4 a = out[i];
    float4 b = out[i + 256];
    a.x = (a.x - mn) * inv; a.y = (a.y - mn) * inv;
    a.z = (a.z - mn) * inv; a.w = (a.w - mn) * inv;
    b.x = (b.x - mn) * inv; b.y = (b.y - mn) * inv;
    b.z = (b.z - mn) * inv; b.w = (b.w - mn) * inv;
    out[i] = a;
    out[i + 256] = b;
}

extern "C" void kernel_launch(void* const* d_in, const int* in_sizes, int n_in,
                              void* d_out, int out_size)
{
    const float* inp  = (const float*)d_in[0];
    const float* mu_z = (const float*)d_in[1];
    const float* sigz = (const float*)d_in[2];
    const float* bxy  = (const float*)d_in[3];
    const float* bz   = (const float*)d_in[4];
    float* out = (float*)d_out;

    static int smem_set = 0;
    if (!smem_set) {
        cudaFuncSetAttribute(k_fused,
            cudaFuncAttributeMaxDynamicSharedMemorySize, SMEM_DYN);
        smem_set = 1;
    }

    // reset global min/max (memset nodes, graph-capturable)
    void *pmin = nullptr, *pmax = nullptr;
    cudaGetSymbolAddress(&pmin, g_minb);
    cudaGetSymbolAddress(&pmax, g_maxb);
    cudaMemsetAsync(pmin, 0xFF, 4);
    cudaMemsetAsync(pmax, 0x00, 4);

    dim3 g(Ww / 64, Hh / 64, OD / 8);   // (8, 8, 4) = 256 blocks
    k_fused<<<g, NT, SMEM_DYN>>>(inp, mu_z, sigz, bxy, bz, out);

    int n4 = OD * HW / 4;               // 2,097,152 float4s
    k_norm<<<n4 / 512, 256>>>((float4*)out);
}

// round 10
// speedup vs baseline: 1.1605x; 1.1605x over previous
#include <cuda_runtime.h>
#include <math.h>
#include <stdint.h>

#define Dd 128
#define Hh 512
#define Ww 512
#define OD 32
#define HW (Hh*Ww)
#define INV_SQRT_2PI 0.3989422804014327f

#define NT 288
#define PCOLS 80                       // staged halo cols (72 data + 8 pad)
#define PLANE_S (72*PCOLS)             // 5760 floats = 1440 granules
#define RING_F (3*PLANE_S)             // 3-stage ring
#define SIN 76                         // s_pl padded stride
#define SMEM_DYN ((RING_F + 72*SIN) * 4)   // 69120 + 21888 = 91008 B

__device__ unsigned g_minb;
__device__ unsigned g_maxb;

__device__ __forceinline__ unsigned f2o(float f) {
    unsigned u = __float_as_uint(f);
    return (u & 0x80000000u) ? ~u : (u | 0x80000000u);
}
__device__ __forceinline__ float o2f(unsigned u) {
    return (u & 0x80000000u) ? __uint_as_float(u ^ 0x80000000u)
                             : __uint_as_float(~u);
}

// ---------------------------------------------------------------------------
// Fused z-conv + y-conv + x-conv + min/max.  Block = 64x64 tile x 8 z-outs.
// THREAD-PRIVATE cp.async ring: halo padded to 72x80 -> 1440 granules = 5 per
// thread; each thread stages and consumes ITS OWN granules, so the only ring
// ordering needed is cp.async.wait_group (no per-plane __syncthreads).
// Granules are 4-aligned and image bounds are multiples of 4, so every
// granule is fully valid or fully zero-filled.  Every 4th plane retires one
// z-convolved 72x72 plane through smem -> in-place y-conv -> x-conv -> store.
// ---------------------------------------------------------------------------
__global__ void __launch_bounds__(NT, 2) k_fused(
    const float* __restrict__ in,
    const float* __restrict__ p_mu, const float* __restrict__ p_sig,
    const float* __restrict__ p_bxy, const float* __restrict__ p_bz,
    float* __restrict__ out)
{
    extern __shared__ __align__(16) float smem[];
    float* ring = smem;                 // [3][5760]
    float* s_pl = smem + RING_F;        // [72][76]
    __shared__ float s_w[9];
    __shared__ float smin[16], smax[16];

    int t   = threadIdx.x;
    int Y0  = blockIdx.x * 64;
    int X0  = blockIdx.y * 64;
    int zo0 = blockIdx.z * 8;
    int zstart = 4 * zo0 - 3;           // input plane at iz=0 (37 planes)

    unsigned sring = (unsigned)__cvta_generic_to_shared(ring);

    uint64_t pol_f;
    asm("createpolicy.fractional.L2::evict_first.b64 %0, 1.0;" : "=l"(pol_f));

    float bz = *p_bz, bxy = *p_bxy;
    float amp = INV_SQRT_2PI * expf(*p_mu + 0.5f * (*p_sig) * (*p_sig));
    float i2bz = 1.0f / (2.0f * bz * bz);
    float wz[9];
#pragma unroll
    for (int k = 0; k < 9; k++) {
        float d = (float)(k - 4);
        wz[k] = expf(-d * d * i2bz) * amp;
    }
    if (t < 9) {                        // xy weights to smem (reg relief)
        float d = (float)(t - 4);
        s_w[t] = expf(-d * d / (2.0f * bxy * bxy));
    }
    // s_w visible after the first retire barrier (before first use)

    float4 acc[3][5];
#pragma unroll
    for (int s = 0; s < 3; s++)
#pragma unroll
        for (int k = 0; k < 5; k++) acc[s][k] = make_float4(0.f,0.f,0.f,0.f);

    float lmin =  3.402823466e38f;
    float lmax = -3.402823466e38f;

    // stage plane P into slot P%3: 5 thread-private granules
#define ISSUE(P) do { if ((P) <= 36) {                                        \
        int z_ = zstart + (P);                                                \
        int zok_ = ((unsigned)z_ < 128u);                                     \
        const float* pz_ = in + (size_t)(zok_ ? z_ : 0) * HW;                 \
        _Pragma("unroll")                                                     \
        for (int k_ = 0; k_ < 5; k_++) {                                      \
            int g_ = t + 288 * k_;                                            \
            int r_ = g_ / 20, cs_ = g_ % 20;                                  \
            int gx_ = X0 - 4 + r_;                                            \
            int gy_ = Y0 - 4 + 4 * cs_;                                       \
            int ok_ = (zok_ && cs_ < 18 && (unsigned)gx_ < 512u &&            \
                       (unsigned)gy_ < 512u) ? 16 : 0;                        \
            int gxc_ = gx_ < 0 ? 0 : (gx_ > 511 ? 511 : gx_);                 \
            int gyc_ = gy_ < 0 ? 0 : (gy_ > 508 ? 508 : gy_);                 \
            const float* gp_ = pz_ + (size_t)gxc_ * 512 + gyc_;               \
            unsigned sa_ = sring + ((((P) % 3) * PLANE_S + 4 * g_) * 4u);     \
            asm volatile(                                                     \
                "cp.async.cg.shared.global.L2::cache_hint "                   \
                "[%0], [%1], 16, %2, %3;"                                     \
                :: "r"(sa_), "l"(gp_), "r"(ok_), "l"(pol_f) : "memory");      \
        }                                                                     \
        asm volatile("cp.async.commit_group;" ::: "memory");                  \
    } } while (0)
#define WG(n) asm volatile("cp.async.wait_group " #n ";" ::: "memory")

    ISSUE(0); ISSUE(1); ISSUE(2);

    size_t outbase = (size_t)X0 * 512 + Y0;

#pragma unroll
    for (int iz = 0; iz < 37; iz++) {
        if (iz <= 34)      WG(2);
        else if (iz == 35) WG(1);
        else               WG(0);

        // my own granules -> registers (thread-private, no barrier)
        float4 v[5];
        const float4* st = reinterpret_cast<const float4*>(
            ring + (iz % 3) * PLANE_S);
#pragma unroll
        for (int k = 0; k < 5; k++) v[k] = st[t + 288 * k];

        ISSUE(iz + 3);                  // refill my slots (read already done)

        const int c = iz >> 2, q = iz & 3;      // compile-time (full unroll)

        if (c <= 7) {                           // tap kz=q for output j=c
            float wv = wz[q];
            int s = c % 3;
#pragma unroll
            for (int k = 0; k < 5; k++) {
                acc[s][k].x += wv * v[k].x; acc[s][k].y += wv * v[k].y;
                acc[s][k].z += wv * v[k].z; acc[s][k].w += wv * v[k].w;
            }
        }
        if (c >= 1 && c <= 8) {                 // tap kz=4+q for j=c-1
            float wv = wz[4 + q];
            int s = (c - 1) % 3;
#pragma unroll
            for (int k = 0; k < 5; k++) {
                acc[s][k].x += wv * v[k].x; acc[s][k].y += wv * v[k].y;
                acc[s][k].z += wv * v[k].z; acc[s][k].w += wv * v[k].w;
            }
        }
        if (q == 0 && c >= 2) {                 // tap kz=8, then RETIRE j=c-2
            const int jout = c - 2;             // 0..7
            const int s = jout % 3;
            float wv = wz[8];
#pragma unroll
            for (int k = 0; k < 5; k++) {
                acc[s][k].x += wv * v[k].x; acc[s][k].y += wv * v[k].y;
                acc[s][k].z += wv * v[k].z; acc[s][k].w += wv * v[k].w;
            }

            // ---- retire: z-convolved plane -> s_pl (float4, my granules) --
#pragma unroll
            for (int k = 0; k < 5; k++) {
                int g = t + 288 * k;
                int r = g / 20, cs = g % 20;
                if (cs < 18)
                    *reinterpret_cast<float4*>(&s_pl[r * SIN + 4 * cs]) =
                        acc[s][k];
                acc[s][k] = make_float4(0.f, 0.f, 0.f, 0.f);
            }
            __syncthreads();

            float wl[9];
#pragma unroll
            for (int k = 0; k < 9; k++) wl[k] = s_w[k];

            // ---- y-conv, in place (72 rows x 4 segs = 288 threads) ----
            {
                int row = t % 72;
                int c0  = (t / 72) * 16;
                float vy[24];
                float4* vp = reinterpret_cast<float4*>(vy);
#pragma unroll
                for (int g4 = 0; g4 < 6; g4++)
                    vp[g4] = *reinterpret_cast<float4*>(
                        &s_pl[row * SIN + c0 + 4 * g4]);
                __syncthreads();        // all reads before in-place writes
                float r_[16];
#pragma unroll
                for (int o = 0; o < 16; o++) {
                    float sv = 0.f;
#pragma unroll
                    for (int k = 0; k < 9; k++) sv += wl[k] * vy[o + k];
                    r_[o] = sv;
                }
#pragma unroll
                for (int g4 = 0; g4 < 4; g4++)
                    *reinterpret_cast<float4*>(&s_pl[row * SIN + c0 + 4 * g4]) =
                        make_float4(r_[4*g4], r_[4*g4+1], r_[4*g4+2], r_[4*g4+3]);
            }
            __syncthreads();

            // ---- x-conv + store + min/max (64 cols x 4 row-segs) ----
            if (t < 256) {
                int col = t & 63;
                int x0  = (t >> 6) * 16;
                float vx[24];
#pragma unroll
                for (int i = 0; i < 24; i++)
                    vx[i] = s_pl[(x0 + i) * SIN + col];
                float* dst = out + (size_t)(zo0 + jout) * HW + outbase
                             + (size_t)x0 * 512 + col;
#pragma unroll
                for (int o = 0; o < 16; o++) {
                    float sv = 0.f;
#pragma unroll
                    for (int k = 0; k < 9; k++) sv += wl[k] * vx[o + k];
                    dst[(size_t)o * 512] = sv;
                    lmin = fminf(lmin, sv);
                    lmax = fmaxf(lmax, sv);
                }
            }
            __syncthreads();            // s_pl reused by next retire
        }
    }
#undef ISSUE
#undef WG

    // ---- one block-level min/max reduction + global atomics ----
#pragma unroll
    for (int o = 16; o > 0; o >>= 1) {
        lmin = fminf(lmin, __shfl_xor_sync(0xFFFFFFFFu, lmin, o));
        lmax = fmaxf(lmax, __shfl_xor_sync(0xFFFFFFFFu, lmax, o));
    }
    if ((t & 31) == 0) { smin[t >> 5] = lmin; smax[t >> 5] = lmax; }
    __syncthreads();
    if (t < 16) {
        lmin = (t < 9) ? smin[t] :  3.402823466e38f;
        lmax = (t < 9) ? smax[t] : -3.402823466e38f;
#pragma unroll
        for (int o = 8; o > 0; o >>= 1) {
            lmin = fminf(lmin, __shfl_xor_sync(0x0000FFFFu, lmin, o));
            lmax = fmaxf(lmax, __shfl_xor_sync(0x0000FFFFu, lmax, o));
        }
        if (t == 0) {
            atomicMin(&g_minb, f2o(lmin));
            atomicMax(&g_maxb, f2o(lmax));
        }
    }
}

// ---------------------------------------------------------------------------
// Normalize: in-place min-max on d_out, 4 float4 per thread (more MLP).
// ---------------------------------------------------------------------------
__global__ void __launch_bounds__(256) k_norm(float4* __restrict__ out)
{
    int i = blockIdx.x * 1024 + threadIdx.x;
    float mn = o2f(g_minb);
    float mx = o2f(g_maxb);
    float inv = 1.0f / (mx - mn);
    float4 a = out[i];
    float4 b = out[i + 256];
    float4 cc = out[i + 512];
    float4 d = out[i + 768];
    a.x=(a.x-mn)*inv; a.y=(a.y-mn)*inv; a.z=(a.z-mn)*inv; a.w=(a.w-mn)*inv;
    b.x=(b.x-mn)*inv; b.y=(b.y-mn)*inv; b.z=(b.z-mn)*inv; b.w=(b.w-mn)*inv;
    cc.x=(cc.x-mn)*inv; cc.y=(cc.y-mn)*inv; cc.z=(cc.z-mn)*inv; cc.w=(cc.w-mn)*inv;
    d.x=(d.x-mn)*inv; d.y=(d.y-mn)*inv; d.z=(d.z-mn)*inv; d.w=(d.w-mn)*inv;
    out[i] = a;
    out[i + 256] = b;
    out[i + 512] = cc;
    out[i + 768] = d;
}

extern "C" void kernel_launch(void* const* d_in, const int* in_sizes, int n_in,
                              void* d_out, int out_size)
{
    const float* inp  = (const float*)d_in[0];
    const float* mu_z = (const float*)d_in[1];
    const float* sigz = (const float*)d_in[2];
    const float* bxy  = (const float*)d_in[3];
    const float* bz   = (const float*)d_in[4];
    float* out = (float*)d_out;

    static int smem_set = 0;
    if (!smem_set) {
        cudaFuncSetAttribute(k_fused,
            cudaFuncAttributeMaxDynamicSharedMemorySize, SMEM_DYN);
        smem_set = 1;
    }

    void *pmin = nullptr, *pmax = nullptr;
    cudaGetSymbolAddress(&pmin, g_minb);
    cudaGetSymbolAddress(&pmax, g_maxb);
    cudaMemsetAsync(pmin, 0xFF, 4);
    cudaMemsetAsync(pmax, 0x00, 4);

    dim3 g(Ww / 64, Hh / 64, OD / 8);   // (8, 8, 4) = 256 blocks
    k_fused<<<g, NT, SMEM_DYN>>>(inp, mu_z, sigz, bxy, bz, out);

    int n4 = OD * HW / 4;               // 2,097,152 float4s
    k_norm<<<n4 / 1024, 256>>>((float4*)out);
}